// round 5
// baseline (speedup 1.0000x reference)
#include <cuda_runtime.h>
#include <math.h>

#define NN 50000
#define EE 400000

__device__ float g_xin [NN*256];
__device__ float g_esc [EE];
__device__ float g_xh  [NN*64];
__device__ float g_alpha[NN*8];
__device__ float g_aexp[EE*8];
__device__ float g_amax[NN*8];
__device__ float g_asum[NN*8];
__device__ float g_agg [NN*64];
__device__ float g_gat1[NN*64];
__device__ float g_xw  [NN*64];
__device__ float g_gcn1[NN*64];
__device__ float g_dinv[NN];
__device__ float g_h1  [NN*32];

__device__ __forceinline__ float sigm(float x){ return __fdividef(1.f, 1.f + __expf(-x)); }
__device__ __forceinline__ float tanh_fast(float x){ return 1.f - __fdividef(2.f, __expf(2.f*x) + 1.f); }
__device__ __forceinline__ void atomicMaxF(float* a, float v){
    if (v >= 0.f) atomicMax((int*)a, __float_as_int(v));
    else          atomicMin((unsigned int*)a, __float_as_uint(v));
}
__device__ __forceinline__ void redAdd4(float* p, float a, float b, float c, float d){
    asm volatile("red.global.add.v4.f32 [%0], {%1,%2,%3,%4};"
                 :: "l"(p), "f"(a), "f"(b), "f"(c), "f"(d) : "memory");
}

// ---- LSTM: 16 lanes per element, one hidden unit per lane ----
__global__ __launch_bounds__(256, 2) void lstm_kernel(
    const float* __restrict__ seq, const int* __restrict__ lens,
    const float* __restrict__ Wih, const float* __restrict__ Whh,
    const float* __restrict__ bvec, const float* __restrict__ dnnW,
    const float* __restrict__ dnnb, int B, int mode)
{
    int lane = threadIdx.x & 31;
    int u = lane & 15;
    unsigned gmask = (lane < 16) ? 0x0000FFFFu : 0xFFFF0000u;
    int gid = (blockIdx.x * blockDim.x + threadIdx.x) >> 4;
    int ngroups = (gridDim.x * blockDim.x) >> 4;

    float wi0[4], wi1[4], bb[4], whh[4][16];
#pragma unroll
    for (int g = 0; g < 4; g++){
        int row = g * 16 + u;
        wi0[g] = Wih[row*2]; wi1[g] = Wih[row*2+1]; bb[g] = bvec[row];
#pragma unroll
        for (int j = 0; j < 16; j++) whh[g][j] = Whh[row*16 + j];
    }
    float dw  = (mode == 1) ? dnnW[u] : 0.f;
    float dbv = (mode == 1) ? dnnb[0] : 0.f;

    for (int e = gid; e < B; e += ngroups){
        float2 v = ((const float2*)seq)[(size_t)e*16 + u];
        int L = lens[e];
        float h = 0.f, c = 0.f;
        for (int t = 0; t < L; t++){
            float x0 = __shfl_sync(gmask, v.x, t, 16);
            float x1 = __shfl_sync(gmask, v.y, t, 16);
            float gi = fmaf(x1, wi1[0], fmaf(x0, wi0[0], bb[0]));
            float gf = fmaf(x1, wi1[1], fmaf(x0, wi0[1], bb[1]));
            float gg = fmaf(x1, wi1[2], fmaf(x0, wi0[2], bb[2]));
            float go = fmaf(x1, wi1[3], fmaf(x0, wi0[3], bb[3]));
#pragma unroll
            for (int j = 0; j < 16; j++){
                float hj = __shfl_sync(gmask, h, j, 16);
                gi = fmaf(hj, whh[0][j], gi);
                gf = fmaf(hj, whh[1][j], gf);
                gg = fmaf(hj, whh[2][j], gg);
                go = fmaf(hj, whh[3][j], go);
            }
            c = fmaf(sigm(gf), c, sigm(gi) * tanh_fast(gg));
            h = sigm(go) * tanh_fast(c);
        }
        if (mode == 0){
            g_xin[(size_t)e*256 + 240 + u] = h;
        } else {
            float val = h * dw;
#pragma unroll
            for (int off = 8; off; off >>= 1) val += __shfl_xor_sync(gmask, val, off, 16);
            if (u == 0) g_esc[e] = val + dbv;
        }
    }
}

__global__ void copy_x_kernel(const float* __restrict__ x){
    int i = blockIdx.x * blockDim.x + threadIdx.x;
    if (i >= NN*60) return;
    int r = i / 60, cq = i % 60;
    ((float4*)g_xin)[r*64 + cq] = ((const float4*)x)[i];
}
__global__ void fill_kernel(float* __restrict__ p, float v, int n){
    int i = blockIdx.x * blockDim.x + threadIdx.x;
    if (i < n) p[i] = v;
}

// ---- register-blocked GEMM, optional K-split [A | A2] at K1 ----
template <int NC>
__global__ __launch_bounds__(256) void gemm_kernel(
    const float* __restrict__ A, int lda, int K1,
    const float* __restrict__ A2, int lda2,
    const float* __restrict__ W, const float* __restrict__ bias,
    float* __restrict__ Out, int M, int K, int act)
{
    constexpr int TPR = NC / 4;
    constexpr int RH  = 256 / TPR;
    int tid = threadIdx.x;
    int c0 = (tid % TPR) * 4;
    int r0 = blockIdx.x * (RH*2) + tid / TPR;
    int r1 = r0 + RH;
    bool v0 = r0 < M, v1 = r1 < M;
    float acc0[4] = {0,0,0,0}, acc1[4] = {0,0,0,0};

    for (int k = 0; k < K; k += 4){
        float a0[4] = {0,0,0,0}, a1[4] = {0,0,0,0};
        const float *p0, *p1;
        if (k < K1){ p0 = A  + (size_t)r0*lda  + k;      p1 = A  + (size_t)r1*lda  + k; }
        else       { p0 = A2 + (size_t)r0*lda2 + (k-K1); p1 = A2 + (size_t)r1*lda2 + (k-K1); }
        if (v0) *(float4*)a0 = *(const float4*)p0;
        if (v1) *(float4*)a1 = *(const float4*)p1;
#pragma unroll
        for (int kk = 0; kk < 4; kk++){
            float4 w = *(const float4*)(W + (size_t)(k+kk)*NC + c0);
            acc0[0]=fmaf(a0[kk],w.x,acc0[0]); acc0[1]=fmaf(a0[kk],w.y,acc0[1]);
            acc0[2]=fmaf(a0[kk],w.z,acc0[2]); acc0[3]=fmaf(a0[kk],w.w,acc0[3]);
            acc1[0]=fmaf(a1[kk],w.x,acc1[0]); acc1[1]=fmaf(a1[kk],w.y,acc1[1]);
            acc1[2]=fmaf(a1[kk],w.z,acc1[2]); acc1[3]=fmaf(a1[kk],w.w,acc1[3]);
        }
    }
#pragma unroll
    for (int i = 0; i < 4; i++){
        float bs = bias ? bias[c0+i] : 0.f;
        acc0[i] += bs; acc1[i] += bs;
        if (act){
            acc0[i] = acc0[i] > 0.f ? acc0[i] : 0.01f*acc0[i];
            acc1[i] = acc1[i] > 0.f ? acc1[i] : 0.01f*acc1[i];
        }
    }
    if (v0) *(float4*)(Out + (size_t)r0*NC + c0) = make_float4(acc0[0],acc0[1],acc0[2],acc0[3]);
    if (v1) *(float4*)(Out + (size_t)r1*NC + c0) = make_float4(acc1[0],acc1[1],acc1[2],acc1[3]);
}

// ---- GAT ----
__global__ void alpha_kernel(const float* __restrict__ att, int H){
    int i = blockIdx.x * blockDim.x + threadIdx.x;
    if (i >= NN*H) return;
    int n = i / H, h = i - n*H;
    int C = 64 / H;
    const float* xr = g_xh + (size_t)n*64 + h*C;
    const float* ar = att + h*C;
    float s = 0.f;
    for (int c = 0; c < C; c++) s = fmaf(xr[c], ar[c], s);
    g_alpha[i] = s;
}
__global__ void gatA_kernel(const int* __restrict__ ei, int H){
    int t = blockIdx.x * blockDim.x + threadIdx.x;
    if (t >= EE*H) return;
    int e = t / H, h = t - e*H;
    int s = ei[e], d = ei[EE+e];
    float a = g_alpha[s*H + h];
    a = a > 0.f ? a : 0.2f*a;
    g_aexp[e*H + h] = a;
    atomicMaxF(&g_amax[d*H + h], a);
}
__global__ void gatB_kernel(const int* __restrict__ ei, int H){
    int t = blockIdx.x * blockDim.x + threadIdx.x;
    if (t >= EE*H) return;
    int e = t / H, h = t - e*H;
    int d = ei[EE+e];
    float ex = __expf(g_aexp[e*H + h] - g_amax[d*H + h]);
    g_aexp[e*H + h] = ex;
    atomicAdd(&g_asum[d*H + h], ex);
}
__global__ void gatC_kernel(const int* __restrict__ ei, int H){
    int t = blockIdx.x * blockDim.x + threadIdx.x;
    int e = t >> 4;
    if (e >= EE) return;
    int l = t & 15;
    int s = ei[e], d = ei[EE+e];
    int h = (l*4*H) >> 6;
    float coef = __fdividef(g_aexp[e*H + h], g_asum[d*H + h]) + g_esc[e];
    float4 xv = *(const float4*)(g_xh + (size_t)s*64 + l*4);
    redAdd4(g_agg + (size_t)d*64 + l*4, xv.x*coef, xv.y*coef, xv.z*coef, xv.w*coef);
}
__global__ void gatFin_kernel(const float* __restrict__ bias, float* __restrict__ outp, int clean){
    int i = blockIdx.x * blockDim.x + threadIdx.x;
    if (i >= NN*64) return;
    int c = i & 63;
    float v = g_agg[i] + g_xh[i] + bias[c];
    if (clean && !isfinite(v)) v = 0.f;
    outp[i] = v;
}

// ---- GCN ----
__global__ void deg_kernel(const int* __restrict__ ei){
    int e = blockIdx.x * blockDim.x + threadIdx.x;
    if (e < EE) atomicAdd(&g_dinv[ei[EE+e]], 1.f);
}
__global__ void dinv_kernel(){
    int n = blockIdx.x * blockDim.x + threadIdx.x;
    if (n < NN) g_dinv[n] = rsqrtf(g_dinv[n] + 1.f);
}
__global__ void gcnE_kernel(const int* __restrict__ ei){
    int t = blockIdx.x * blockDim.x + threadIdx.x;
    int e = t >> 4;
    if (e >= EE) return;
    int l = t & 15;
    int s = ei[e], d = ei[EE+e];
    float nm = g_dinv[s] * g_dinv[d];
    float4 xv = *(const float4*)(g_xw + (size_t)s*64 + l*4);
    redAdd4(g_agg + (size_t)d*64 + l*4, xv.x*nm, xv.y*nm, xv.z*nm, xv.w*nm);
}
__global__ void gcnFin_kernel(const float* __restrict__ bias, float* __restrict__ outp){
    int i = blockIdx.x * blockDim.x + threadIdx.x;
    if (i >= NN*64) return;
    int n = i >> 6, c = i & 63;
    float di = g_dinv[n];
    float v = g_agg[i] + g_xw[i]*di*di + bias[c];
    outp[i] = v > 0.f ? v : 0.01f*v;
}

// ---- classifier layers 2+3 ----
__global__ void cls23_kernel(const float* __restrict__ W2, const float* __restrict__ b2,
                             const float* __restrict__ W3, const float* __restrict__ b3,
                             float* __restrict__ out){
    __shared__ float sW2[32*16], sW3[16*4], sb2[16], sb3[4];
    for (int i = threadIdx.x; i < 512; i += 256) sW2[i] = W2[i];
    for (int i = threadIdx.x; i < 64;  i += 256) sW3[i] = W3[i];
    if (threadIdx.x < 16) sb2[threadIdx.x] = b2[threadIdx.x];
    if (threadIdx.x < 4)  sb3[threadIdx.x] = b3[threadIdx.x];
    __syncthreads();
    int n = blockIdx.x * blockDim.x + threadIdx.x;
    if (n >= NN) return;
    float h2[16];
#pragma unroll
    for (int j = 0; j < 16; j++) h2[j] = sb2[j];
#pragma unroll
    for (int q = 0; q < 8; q++){
        float4 hv = *(const float4*)(g_h1 + (size_t)n*32 + q*4);
        float hh[4] = {hv.x, hv.y, hv.z, hv.w};
#pragma unroll
        for (int kk = 0; kk < 4; kk++)
#pragma unroll
            for (int j = 0; j < 16; j++) h2[j] = fmaf(hh[kk], sW2[(q*4+kk)*16 + j], h2[j]);
    }
#pragma unroll
    for (int j = 0; j < 16; j++) h2[j] = h2[j] > 0.f ? h2[j] : 0.01f*h2[j];
    float o[4] = {sb3[0], sb3[1], sb3[2], sb3[3]};
#pragma unroll
    for (int k = 0; k < 16; k++)
#pragma unroll
        for (int j = 0; j < 4; j++) o[j] = fmaf(h2[k], sW3[k*4 + j], o[j]);
    *(float4*)(out + (size_t)n*4) = make_float4(o[0], o[1], o[2], o[3]);
}

extern "C" void kernel_launch(void* const* d_in, const int* in_sizes, int n_in,
                              void* d_out, int out_size)
{
    const float* x    = (const float*)d_in[0];
    const float* eseq = (const float*)d_in[1];
    const float* nseq = (const float*)d_in[2];
    const float* Wih  = (const float*)d_in[3];
    const float* Whh  = (const float*)d_in[4];
    const float* lb   = (const float*)d_in[5];
    const float* dW   = (const float*)d_in[6];
    const float* dbv  = (const float*)d_in[7];
    const float* g1W  = (const float*)d_in[8];
    const float* g1att= (const float*)d_in[9];
    const float* g1b  = (const float*)d_in[10];
    const float* g2W  = (const float*)d_in[11];
    const float* g2att= (const float*)d_in[12];
    const float* g2b  = (const float*)d_in[13];
    const float* n1W  = (const float*)d_in[14];
    const float* n1b  = (const float*)d_in[15];
    const float* n2W  = (const float*)d_in[16];
    const float* n2b  = (const float*)d_in[17];
    const float* c1W  = (const float*)d_in[18];
    const float* c1b  = (const float*)d_in[19];
    const float* c2W  = (const float*)d_in[20];
    const float* c2b  = (const float*)d_in[21];
    const float* c3W  = (const float*)d_in[22];
    const float* c3b  = (const float*)d_in[23];
    const int*   ei   = (const int*)d_in[24];
    const int*   elen = (const int*)d_in[25];
    const int*   nlen = (const int*)d_in[26];

    float* out  = (float*)d_out;
    float* xgcn = out + (size_t)NN*4;
    float* xgat = xgcn + (size_t)NN*64;

    float *p_xin, *p_xh, *p_gat1, *p_xw, *p_gcn1, *p_h1, *p_amax, *p_asum, *p_agg, *p_dinv;
    cudaGetSymbolAddress((void**)&p_xin,  g_xin);
    cudaGetSymbolAddress((void**)&p_xh,   g_xh);
    cudaGetSymbolAddress((void**)&p_gat1, g_gat1);
    cudaGetSymbolAddress((void**)&p_xw,   g_xw);
    cudaGetSymbolAddress((void**)&p_gcn1, g_gcn1);
    cudaGetSymbolAddress((void**)&p_h1,   g_h1);
    cudaGetSymbolAddress((void**)&p_amax, g_amax);
    cudaGetSymbolAddress((void**)&p_asum, g_asum);
    cudaGetSymbolAddress((void**)&p_agg,  g_agg);
    cudaGetSymbolAddress((void**)&p_dinv, g_dinv);

    auto cdiv = [](int a, int b){ return (a + b - 1) / b; };
    const float NINF = -INFINITY;

    // temporal branches
    lstm_kernel<<<512, 256>>>(nseq, nlen, Wih, Whh, lb, dW, dbv, NN, 0);
    copy_x_kernel<<<cdiv(NN*60,256), 256>>>(x);
    lstm_kernel<<<2048, 256>>>(eseq, elen, Wih, Whh, lb, dW, dbv, EE, 1);

    // GCN degree
    fill_kernel<<<cdiv(NN,256),256>>>(p_dinv, 0.f, NN);
    deg_kernel<<<cdiv(EE,256),256>>>(ei);
    dinv_kernel<<<cdiv(NN,256),256>>>();

    // GAT1 (H=8)
    gemm_kernel<64><<<cdiv(NN,32),256>>>(p_xin,256,1<<30,nullptr,0,g1W,nullptr,p_xh,NN,256,0);
    alpha_kernel<<<cdiv(NN*8,256),256>>>(g1att, 8);
    fill_kernel<<<cdiv(NN*8,256),256>>>(p_amax, NINF, NN*8);
    fill_kernel<<<cdiv(NN*8,256),256>>>(p_asum, 0.f, NN*8);
    fill_kernel<<<cdiv(NN*64,256),256>>>(p_agg, 0.f, NN*64);
    gatA_kernel<<<cdiv(EE*8,256),256>>>(ei, 8);
    gatB_kernel<<<cdiv(EE*8,256),256>>>(ei, 8);
    gatC_kernel<<<cdiv(EE*16,256),256>>>(ei, 8);
    gatFin_kernel<<<cdiv(NN*64,256),256>>>(g1b, p_gat1, 0);

    // GAT2 (H=1)
    gemm_kernel<64><<<cdiv(NN,32),256>>>(p_gat1,64,1<<30,nullptr,0,g2W,nullptr,p_xh,NN,64,0);
    alpha_kernel<<<cdiv(NN,256),256>>>(g2att, 1);
    fill_kernel<<<cdiv(NN,256),256>>>(p_amax, NINF, NN);
    fill_kernel<<<cdiv(NN,256),256>>>(p_asum, 0.f, NN);
    fill_kernel<<<cdiv(NN*64,256),256>>>(p_agg, 0.f, NN*64);
    gatA_kernel<<<cdiv(EE,256),256>>>(ei, 1);
    gatB_kernel<<<cdiv(EE,256),256>>>(ei, 1);
    gatC_kernel<<<cdiv(EE*16,256),256>>>(ei, 1);
    gatFin_kernel<<<cdiv(NN*64,256),256>>>(g2b, xgat, 1);

    // GCN1
    gemm_kernel<64><<<cdiv(NN,32),256>>>(p_xin,256,1<<30,nullptr,0,n1W,nullptr,p_xw,NN,256,0);
    fill_kernel<<<cdiv(NN*64,256),256>>>(p_agg, 0.f, NN*64);
    gcnE_kernel<<<cdiv(EE*16,256),256>>>(ei);
    gcnFin_kernel<<<cdiv(NN*64,256),256>>>(n1b, p_gcn1);

    // GCN2
    gemm_kernel<64><<<cdiv(NN,32),256>>>(p_gcn1,64,1<<30,nullptr,0,n2W,nullptr,p_xw,NN,64,0);
    fill_kernel<<<cdiv(NN*64,256),256>>>(p_agg, 0.f, NN*64);
    gcnE_kernel<<<cdiv(EE*16,256),256>>>(ei);
    gcnFin_kernel<<<cdiv(NN*64,256),256>>>(n2b, xgcn);

    // classifier
    gemm_kernel<32><<<cdiv(NN,64),256>>>(p_xin,256,256,xgcn,64,c1W,c1b,p_h1,NN,320,1);
    cls23_kernel<<<cdiv(NN,256),256>>>(c2W, c2b, c3W, c3b, out);
}